// round 1
// baseline (speedup 1.0000x reference)
#include <cuda_runtime.h>
#include <math.h>

#define NN 50000
#define NE 800000
#define D 128
#define LDA 132   // padded smem row (floats), 16B-aligned rows

// ---------------- scratch (device globals; no allocation allowed) ----------
__device__ float g_deg[NN];
__device__ float g_dinv[NN];
__device__ float g_xs[NN * D];     // dinv[i] * x[i]
__device__ float g_agg[NN * D];    // accumulated (A+I) * xs
__device__ float g_Wf[3 * D * D];  // fused Wc_g @ Wl_g_top
__device__ float g_bf[3 * D];      // fused bc_g @ Wl_g_top + bl_g

// ---------------- degree -----------------------------------------------------
__global__ void k_init_deg() {
    int i = blockIdx.x * blockDim.x + threadIdx.x;
    if (i < NN) g_deg[i] = 1.0f;  // self-loop
}

__global__ void k_count(const int* __restrict__ dst) {
    int e = blockIdx.x * blockDim.x + threadIdx.x;
    if (e < NE) atomicAdd(&g_deg[dst[e]], 1.0f);
}

// xs = dinv * x ; agg initialized with self-loop term (= xs)
__global__ void k_prescale(const float* __restrict__ x) {
    int idx = blockIdx.x * blockDim.x + threadIdx.x;  // over NN*32 float4 slots
    if (idx >= NN * 32) return;
    int i = idx >> 5, c = idx & 31;
    float dv = rsqrtf(g_deg[i]);
    float4 v = ((const float4*)x)[idx];
    v.x *= dv; v.y *= dv; v.z *= dv; v.w *= dv;
    ((float4*)g_xs)[idx] = v;
    ((float4*)g_agg)[idx] = v;
    if (c == 0) g_dinv[i] = dv;
}

// warp per edge: gather xs[src] (L2-resident), vector-red into agg[dst]
__global__ void k_edges(const int* __restrict__ src, const int* __restrict__ dst) {
    int idx = blockIdx.x * blockDim.x + threadIdx.x;  // NE*32 < 2^31
    if (idx >= NE * 32) return;
    int e = idx >> 5, lane = idx & 31;
    int s = __ldg(&src[e]);
    int d2 = __ldg(&dst[e]);
    float4 v = ((const float4*)g_xs)[s * 32 + lane];
    float4* p = ((float4*)g_agg) + d2 * 32 + lane;
    asm volatile("red.global.add.v4.f32 [%0], {%1,%2,%3,%4};"
                 :: "l"(p), "f"(v.x), "f"(v.y), "f"(v.z), "f"(v.w) : "memory");
}

// ---------------- fused weight precompute: Wf_g = Wc_g @ Wl_g[0:128,:] ------
__global__ void k_fuse(const float* __restrict__ Wc_z, const float* __restrict__ Wl_z,
                       const float* __restrict__ bc_z, const float* __restrict__ bl_z,
                       const float* __restrict__ Wc_r, const float* __restrict__ Wl_r,
                       const float* __restrict__ bc_r, const float* __restrict__ bl_r,
                       const float* __restrict__ Wc_h, const float* __restrict__ Wl_h,
                       const float* __restrict__ bc_h, const float* __restrict__ bl_h) {
    int g = blockIdx.y;
    const float* Wc = (g == 0) ? Wc_z : (g == 1) ? Wc_r : Wc_h;
    const float* Wl = (g == 0) ? Wl_z : (g == 1) ? Wl_r : Wl_h;
    const float* bc = (g == 0) ? bc_z : (g == 1) ? bc_r : bc_h;
    const float* bl = (g == 0) ? bl_z : (g == 1) ? bl_r : bl_h;
    int i = blockIdx.x;
    int j = threadIdx.x;
    float s = 0.0f;
    #pragma unroll 8
    for (int k = 0; k < D; ++k) s += Wc[i * D + k] * Wl[k * D + j];
    g_Wf[g * D * D + i * D + j] = s;
    if (i == 0) {
        float b = bl[j];
        #pragma unroll 8
        for (int k = 0; k < D; ++k) b += bc[k] * Wl[k * D + j];
        g_bf[g * D + j] = b;
    }
}

// ---------------- main fused GRU tile kernel --------------------------------
// block = 512 threads = 32x16 thread grid, each thread owns a 4x8 output tile.
// acc += As(128x128, smem) @ Bg(128x128, global/L2), B staged 32 rows at a time.
__device__ __forceinline__ void gemm_acc(const float* __restrict__ As,
                                         const float* __restrict__ Bg,
                                         float acc[4][8], float* Bs,
                                         int tid, int tm, int tn) {
    #pragma unroll 1
    for (int kc = 0; kc < 4; ++kc) {
        const float4* bsrc = (const float4*)(Bg + kc * 32 * D);
        float4* bdst = (float4*)Bs;
        bdst[tid] = bsrc[tid];
        bdst[tid + 512] = bsrc[tid + 512];
        __syncthreads();
        const float* abase = As + kc * 32;
        #pragma unroll 2
        for (int k4 = 0; k4 < 32; k4 += 4) {
            float4 A0 = *(const float4*)(abase + (tm * 4 + 0) * LDA + k4);
            float4 A1 = *(const float4*)(abase + (tm * 4 + 1) * LDA + k4);
            float4 A2 = *(const float4*)(abase + (tm * 4 + 2) * LDA + k4);
            float4 A3 = *(const float4*)(abase + (tm * 4 + 3) * LDA + k4);
            float av[4][4] = {{A0.x, A0.y, A0.z, A0.w},
                              {A1.x, A1.y, A1.z, A1.w},
                              {A2.x, A2.y, A2.z, A2.w},
                              {A3.x, A3.y, A3.z, A3.w}};
            #pragma unroll
            for (int kk = 0; kk < 4; ++kk) {
                float4 b0 = *(const float4*)(Bs + (k4 + kk) * D + tn * 8);
                float4 b1 = *(const float4*)(Bs + (k4 + kk) * D + tn * 8 + 4);
                float bv[8] = {b0.x, b0.y, b0.z, b0.w, b1.x, b1.y, b1.z, b1.w};
                #pragma unroll
                for (int i = 0; i < 4; ++i)
                    #pragma unroll
                    for (int j = 0; j < 8; ++j)
                        acc[i][j] += av[i][kk] * bv[j];
            }
        }
        __syncthreads();
    }
}

__device__ __forceinline__ float sigm(float x) { return 1.0f / (1.0f + expf(-x)); }

__global__ void __launch_bounds__(512, 1)
k_main(const float* __restrict__ h,
       const float* __restrict__ Wl_z, const float* __restrict__ Wl_r,
       const float* __restrict__ Wl_h,
       const float* __restrict__ W_lin, const float* __restrict__ b_lin,
       float* __restrict__ out) {
    extern __shared__ float sm[];
    float* xa = sm;                // 128 x LDA : x_agg tile (post-scaled)
    float* hs = xa + D * LDA;      // 128 x LDA : h tile, later relu(h0)
    float* hr = hs + D * LDA;      // 128 x LDA : h*R tile
    float* Bs = hr + D * LDA;      // 32 x 128  : B stage
    int tid = threadIdx.x;
    int tn = tid & 15;   // col group (8 cols)
    int tm = tid >> 4;   // row group (4 rows)
    int nb = blockIdx.x * D;

    // load xa (= dinv * agg) and h tile
    for (int idx = tid; idx < D * 32; idx += 512) {
        int r = idx >> 5, c = idx & 31;
        int node = nb + r;
        float4 va = {0, 0, 0, 0}, vh = {0, 0, 0, 0};
        if (node < NN) {
            float dv = g_dinv[node];
            va = ((const float4*)g_agg)[node * 32 + c];
            va.x *= dv; va.y *= dv; va.z *= dv; va.w *= dv;
            vh = ((const float4*)h)[node * 32 + c];
        }
        *((float4*)(xa + r * LDA) + c) = va;
        *((float4*)(hs + r * LDA) + c) = vh;
    }
    __syncthreads();

    float acc[4][8], Zr[4][8];

    // ---- stage 1: Z = sigmoid(xa@Wf_z + h@Wl_z_bot + bf_z)
    #pragma unroll
    for (int i = 0; i < 4; ++i)
        #pragma unroll
        for (int j = 0; j < 8; ++j) acc[i][j] = 0.0f;
    gemm_acc(xa, g_Wf, acc, Bs, tid, tm, tn);
    gemm_acc(hs, Wl_z + D * D, acc, Bs, tid, tm, tn);
    #pragma unroll
    for (int i = 0; i < 4; ++i)
        #pragma unroll
        for (int j = 0; j < 8; ++j)
            Zr[i][j] = sigm(acc[i][j] + g_bf[tn * 8 + j]);

    // ---- stage 2: R = sigmoid(xa@Wf_r + h@Wl_r_bot + bf_r); hr = h*R
    #pragma unroll
    for (int i = 0; i < 4; ++i)
        #pragma unroll
        for (int j = 0; j < 8; ++j) acc[i][j] = 0.0f;
    gemm_acc(xa, g_Wf + D * D, acc, Bs, tid, tm, tn);
    gemm_acc(hs, Wl_r + D * D, acc, Bs, tid, tm, tn);
    #pragma unroll
    for (int i = 0; i < 4; ++i) {
        int m = tm * 4 + i;
        #pragma unroll
        for (int j = 0; j < 8; ++j) {
            int n = tn * 8 + j;
            float R = sigm(acc[i][j] + g_bf[D + n]);
            hr[m * LDA + n] = hs[m * LDA + n] * R;
        }
    }
    __syncthreads();

    // ---- stage 3: Ht = tanh(xa@Wf_h + hr@Wl_h_bot + bf_h); h0 = Z*h+(1-Z)*Ht
    #pragma unroll
    for (int i = 0; i < 4; ++i)
        #pragma unroll
        for (int j = 0; j < 8; ++j) acc[i][j] = 0.0f;
    gemm_acc(xa, g_Wf + 2 * D * D, acc, Bs, tid, tm, tn);
    gemm_acc(hr, Wl_h + D * D, acc, Bs, tid, tm, tn);
    float* out_h = out + (long long)NN * D;
    #pragma unroll
    for (int i = 0; i < 4; ++i) {
        int m = tm * 4 + i;
        int node = nb + m;
        #pragma unroll
        for (int j = 0; j < 8; ++j) {
            int n = tn * 8 + j;
            float Ht = tanhf(acc[i][j] + g_bf[2 * D + n]);
            float hv = hs[m * LDA + n];
            float h0 = Zr[i][j] * hv + (1.0f - Zr[i][j]) * Ht;
            if (node < NN) out_h[node * D + n] = h0;
            hs[m * LDA + n] = fmaxf(h0, 0.0f);  // relu(h0), own element only
        }
    }
    __syncthreads();

    // ---- stage 4: z_out = relu(h0) @ W_lin + b_lin
    #pragma unroll
    for (int i = 0; i < 4; ++i)
        #pragma unroll
        for (int j = 0; j < 8; ++j) acc[i][j] = 0.0f;
    gemm_acc(hs, W_lin, acc, Bs, tid, tm, tn);
    #pragma unroll
    for (int i = 0; i < 4; ++i) {
        int node = nb + tm * 4 + i;
        if (node < NN) {
            #pragma unroll
            for (int j = 0; j < 8; ++j) {
                int n = tn * 8 + j;
                out[node * D + n] = acc[i][j] + b_lin[n];
            }
        }
    }
}

// ---------------- launch -----------------------------------------------------
extern "C" void kernel_launch(void* const* d_in, const int* in_sizes, int n_in,
                              void* d_out, int out_size) {
    const float* node_feat = (const float*)d_in[0];
    const int*   src       = (const int*)d_in[1];
    const int*   dst       = (const int*)d_in[2];
    const float* h         = (const float*)d_in[3];
    const float* Wc_z = (const float*)d_in[4];
    const float* bc_z = (const float*)d_in[5];
    const float* Wl_z = (const float*)d_in[6];
    const float* bl_z = (const float*)d_in[7];
    const float* Wc_r = (const float*)d_in[8];
    const float* bc_r = (const float*)d_in[9];
    const float* Wl_r = (const float*)d_in[10];
    const float* bl_r = (const float*)d_in[11];
    const float* Wc_h = (const float*)d_in[12];
    const float* bc_h = (const float*)d_in[13];
    const float* Wl_h = (const float*)d_in[14];
    const float* bl_h = (const float*)d_in[15];
    const float* W_lin = (const float*)d_in[16];
    const float* b_lin = (const float*)d_in[17];
    float* out = (float*)d_out;

    const int smem = 3 * D * LDA * sizeof(float) + 32 * D * sizeof(float);
    cudaFuncSetAttribute(k_main, cudaFuncAttributeMaxDynamicSharedMemorySize, smem);

    k_init_deg<<<(NN + 255) / 256, 256>>>();
    k_count<<<(NE + 255) / 256, 256>>>(dst);
    k_prescale<<<(NN * 32 + 255) / 256, 256>>>(node_feat);
    k_edges<<<(NE * 32) / 256, 256>>>(src, dst);
    k_fuse<<<dim3(D, 3), D>>>(Wc_z, Wl_z, bc_z, bl_z,
                              Wc_r, Wl_r, bc_r, bl_r,
                              Wc_h, Wl_h, bc_h, bl_h);
    k_main<<<(NN + D - 1) / D, 512, smem>>>(h, Wl_z, Wl_r, Wl_h, W_lin, b_lin, out);
}